// round 1
// baseline (speedup 1.0000x reference)
#include <cuda_runtime.h>

#define EMB   1024
#define HEADS 16
#define HDIM  64
#define SEQ   2048
#define BATCH 4
#define MTOT  (BATCH * SEQ)   // 8192

// ---------------------------------------------------------------------------
// Scratch (device globals: no runtime allocation allowed)
// ---------------------------------------------------------------------------
__device__ float g_q[(size_t)BATCH * HEADS * SEQ * HDIM];  // [B,H,S,Dh]
__device__ float g_k[(size_t)BATCH * HEADS * SEQ * HDIM];
__device__ float g_v[(size_t)BATCH * HEADS * SEQ * HDIM];
__device__ float g_o[(size_t)MTOT * EMB];                  // [B*S, E] attn output

// ---------------------------------------------------------------------------
// Tiled fp32 GEMM:  C = A(MxK) * B(NxK)^T + bias
// MODE 0: C[m*N + n]
// MODE 1: head-split: C[((b*H + h)*SEQ + s)*HDIM + d]  with m=b*SEQ+s, n=h*HDIM+d
// Block tile 64x64, 256 threads, 4x4 per thread, K-tile 16.
// ---------------------------------------------------------------------------
template <int MODE>
__global__ __launch_bounds__(256)
void gemm_kernel(const float* __restrict__ A, const float* __restrict__ B,
                 const float* __restrict__ bias, float* __restrict__ C,
                 int M, int N, int K)
{
    __shared__ float As[16][68];   // [k][m], padded: conflict-free stores+loads
    __shared__ float Bs[16][68];   // [k][n]

    const int bm = blockIdx.y * 64;
    const int bn = blockIdx.x * 64;
    const int tid = threadIdx.x;
    const int tx = tid & 15;       // 0..15  (n direction)
    const int ty = tid >> 4;       // 0..15  (m direction)

    const int lrow = tid >> 2;         // 0..63 (tile row to load)
    const int lk4  = (tid & 3) * 4;    // 0,4,8,12 (k offset, float4)

    float c[4][4];
#pragma unroll
    for (int i = 0; i < 4; i++)
#pragma unroll
        for (int j = 0; j < 4; j++) c[i][j] = 0.f;

    for (int k0 = 0; k0 < K; k0 += 16) {
        float4 av = *(const float4*)&A[(size_t)(bm + lrow) * K + k0 + lk4];
        float4 bv = *(const float4*)&B[(size_t)(bn + lrow) * K + k0 + lk4];
        As[lk4 + 0][lrow] = av.x;
        As[lk4 + 1][lrow] = av.y;
        As[lk4 + 2][lrow] = av.z;
        As[lk4 + 3][lrow] = av.w;
        Bs[lk4 + 0][lrow] = bv.x;
        Bs[lk4 + 1][lrow] = bv.y;
        Bs[lk4 + 2][lrow] = bv.z;
        Bs[lk4 + 3][lrow] = bv.w;
        __syncthreads();

#pragma unroll
        for (int kk = 0; kk < 16; kk++) {
            float4 a = *(const float4*)&As[kk][ty * 4];
            float4 b = *(const float4*)&Bs[kk][tx * 4];
            c[0][0] += a.x * b.x; c[0][1] += a.x * b.y; c[0][2] += a.x * b.z; c[0][3] += a.x * b.w;
            c[1][0] += a.y * b.x; c[1][1] += a.y * b.y; c[1][2] += a.y * b.z; c[1][3] += a.y * b.w;
            c[2][0] += a.z * b.x; c[2][1] += a.z * b.y; c[2][2] += a.z * b.z; c[2][3] += a.z * b.w;
            c[3][0] += a.w * b.x; c[3][1] += a.w * b.y; c[3][2] += a.w * b.z; c[3][3] += a.w * b.w;
        }
        __syncthreads();
    }

#pragma unroll
    for (int i = 0; i < 4; i++) {
        const int m = bm + ty * 4 + i;
#pragma unroll
        for (int j = 0; j < 4; j++) {
            const int n = bn + tx * 4 + j;
            const float val = c[i][j] + bias[n];
            if (MODE == 0) {
                C[(size_t)m * N + n] = val;
            } else {
                const int b = m / SEQ, s = m % SEQ;
                const int h = n / HDIM, d = n % HDIM;
                C[(((size_t)(b * HEADS + h)) * SEQ + s) * HDIM + d] = val;
            }
        }
    }
}

// ---------------------------------------------------------------------------
// Flash-style attention. Grid: (SEQ/128, BATCH*HEADS). 128 threads.
// Each thread owns one query row (q + acc in registers).
// K/V staged in smem, 64 keys per tile, online softmax in chunks of 16 keys.
// ---------------------------------------------------------------------------
__global__ __launch_bounds__(128)
void attn_kernel(const float* __restrict__ Q, const float* __restrict__ K,
                 const float* __restrict__ V, float* __restrict__ O)
{
    __shared__ float4 Ks[64][16];   // 64 keys x 64 dims
    __shared__ float4 Vs[64][16];

    const int bh  = blockIdx.y;          // 0..63  (b*HEADS + h)
    const int q0  = blockIdx.x * 128;    // query tile base
    const int tid = threadIdx.x;
    const float scale = 1.0f / 32.0f;    // 1/sqrt(EMB)

    // Load this thread's query row, pre-scaled.
    float4 q[16];
    const float4* Qrow = (const float4*)&Q[((size_t)bh * SEQ + q0 + tid) * HDIM];
#pragma unroll
    for (int i = 0; i < 16; i++) {
        float4 t = Qrow[i];
        t.x *= scale; t.y *= scale; t.z *= scale; t.w *= scale;
        q[i] = t;
    }

    float4 acc[16];
#pragma unroll
    for (int i = 0; i < 16; i++) acc[i] = make_float4(0.f, 0.f, 0.f, 0.f);
    float m = -1e30f;
    float l = 0.f;

    const float4* Kg = (const float4*)&K[(size_t)bh * SEQ * HDIM];
    const float4* Vg = (const float4*)&V[(size_t)bh * SEQ * HDIM];

    for (int kt = 0; kt < SEQ; kt += 64) {
        // Stage 64 keys + values (coalesced float4).
        const int base = kt * 16;   // float4 index of tile start
#pragma unroll
        for (int i = 0; i < 8; i++) {
            const int f = tid + i * 128;      // 0..1023
            ((float4*)Ks)[f] = Kg[base + f];
            ((float4*)Vs)[f] = Vg[base + f];
        }
        __syncthreads();

#pragma unroll
        for (int jc = 0; jc < 4; jc++) {
            // scores for 16 keys
            float s[16];
#pragma unroll
            for (int j = 0; j < 16; j++) s[j] = 0.f;
#pragma unroll
            for (int d4 = 0; d4 < 16; d4++) {
                const float4 qv = q[d4];
#pragma unroll
                for (int j = 0; j < 16; j++) {
                    const float4 kv = Ks[jc * 16 + j][d4];
                    s[j] += qv.x * kv.x;
                    s[j] += qv.y * kv.y;
                    s[j] += qv.z * kv.z;
                    s[j] += qv.w * kv.w;
                }
            }
            // online softmax update
            float mnew = m;
#pragma unroll
            for (int j = 0; j < 16; j++) mnew = fmaxf(mnew, s[j]);
            const float corr = __expf(m - mnew);
            m = mnew;
            l *= corr;
            float ps = 0.f;
#pragma unroll
            for (int j = 0; j < 16; j++) {
                s[j] = __expf(s[j] - mnew);
                ps += s[j];
            }
            l += ps;
#pragma unroll
            for (int d4 = 0; d4 < 16; d4++) {
                acc[d4].x *= corr; acc[d4].y *= corr;
                acc[d4].z *= corr; acc[d4].w *= corr;
            }
            // accumulate P*V
#pragma unroll
            for (int j = 0; j < 16; j++) {
                const float pj = s[j];
#pragma unroll
                for (int d4 = 0; d4 < 16; d4++) {
                    const float4 vv = Vs[jc * 16 + j][d4];
                    acc[d4].x += pj * vv.x;
                    acc[d4].y += pj * vv.y;
                    acc[d4].z += pj * vv.z;
                    acc[d4].w += pj * vv.w;
                }
            }
        }
        __syncthreads();
    }

    const float inv = 1.0f / l;
    const int b = bh / HEADS;
    const int h = bh % HEADS;
    float4* Orow = (float4*)&O[((size_t)(b * SEQ + q0 + tid)) * EMB + h * HDIM];
#pragma unroll
    for (int d4 = 0; d4 < 16; d4++) {
        float4 t = acc[d4];
        t.x *= inv; t.y *= inv; t.z *= inv; t.w *= inv;
        Orow[d4] = t;
    }
}

// ---------------------------------------------------------------------------
// Launch
// ---------------------------------------------------------------------------
extern "C" void kernel_launch(void* const* d_in, const int* in_sizes, int n_in,
                              void* d_out, int out_size)
{
    const float* x  = (const float*)d_in[0];
    const float* Wq = (const float*)d_in[1];
    const float* bq = (const float*)d_in[2];
    const float* Wk = (const float*)d_in[3];
    const float* bk = (const float*)d_in[4];
    const float* Wv = (const float*)d_in[5];
    const float* bv = (const float*)d_in[6];
    const float* Wo = (const float*)d_in[7];
    const float* bo = (const float*)d_in[8];
    float* out = (float*)d_out;

    float *dq, *dk, *dv, *doo;
    cudaGetSymbolAddress((void**)&dq,  g_q);
    cudaGetSymbolAddress((void**)&dk,  g_k);
    cudaGetSymbolAddress((void**)&dv,  g_v);
    cudaGetSymbolAddress((void**)&doo, g_o);

    dim3 ggrid(EMB / 64, MTOT / 64);   // (16, 128)
    gemm_kernel<1><<<ggrid, 256>>>(x, Wq, bq, dq, MTOT, EMB, EMB);
    gemm_kernel<1><<<ggrid, 256>>>(x, Wk, bk, dk, MTOT, EMB, EMB);
    gemm_kernel<1><<<ggrid, 256>>>(x, Wv, bv, dv, MTOT, EMB, EMB);

    dim3 agrid(SEQ / 128, BATCH * HEADS);  // (16, 64)
    attn_kernel<<<agrid, 128>>>(dq, dk, dv, doo);

    gemm_kernel<0><<<ggrid, 256>>>(doo, Wo, bo, out, MTOT, EMB, EMB);
}

// round 2
// speedup vs baseline: 5.5304x; 5.5304x over previous
#include <cuda_runtime.h>

#define EMB   1024
#define HEADS 16
#define HDIM  64
#define SEQ   2048
#define BATCH 4
#define MTOT  (BATCH * SEQ)   // 8192

// ---------------------------------------------------------------------------
// Scratch (device globals: no runtime allocation allowed)
// ---------------------------------------------------------------------------
__device__ float g_q[(size_t)BATCH * HEADS * SEQ * HDIM];  // [B,H,S,Dh]
__device__ float g_k[(size_t)BATCH * HEADS * SEQ * HDIM];
__device__ float g_v[(size_t)BATCH * HEADS * SEQ * HDIM];
__device__ float g_o[(size_t)MTOT * EMB];                  // [B*S, E] attn output

// ---------------------------------------------------------------------------
// Helpers: tf32 convert + mma.sync m16n8k8 (row.col, f32 accum)
// ---------------------------------------------------------------------------
__device__ __forceinline__ unsigned f2tf(float f) {
    unsigned u;
    asm("cvt.rna.tf32.f32 %0, %1;" : "=r"(u) : "f"(f));
    return u;
}

__device__ __forceinline__ void mma_tf32(float* d, const unsigned* a, const unsigned* b) {
    asm volatile(
        "mma.sync.aligned.m16n8k8.row.col.f32.tf32.tf32.f32 "
        "{%0,%1,%2,%3}, {%4,%5,%6,%7}, {%8,%9}, {%0,%1,%2,%3};\n"
        : "+f"(d[0]), "+f"(d[1]), "+f"(d[2]), "+f"(d[3])
        : "r"(a[0]), "r"(a[1]), "r"(a[2]), "r"(a[3]), "r"(b[0]), "r"(b[1]));
}

// ---------------------------------------------------------------------------
// tf32 GEMM:  C = A(MxK) * B(NxK)^T + bias
// MODE 0: C[m*N + n]
// MODE 1: head-split: C[((b*H + h)*SEQ + s)*HDIM + d]
// Block tile 128x128, BK=32, 256 threads (8 warps: 2M x 4N, warp tile 64x32).
// ---------------------------------------------------------------------------
template <int MODE>
__global__ __launch_bounds__(256)
void gemm_tf32(const float* __restrict__ A, const float* __restrict__ B,
               const float* __restrict__ bias, float* __restrict__ C,
               int M, int N, int K)
{
    __shared__ unsigned As[128][36];   // [m][k], pad 4 -> frag reads conflict-free
    __shared__ unsigned Bs[128][36];   // [n][k]

    const int tid  = threadIdx.x;
    const int warp = tid >> 5;
    const int lane = tid & 31;
    const int g = lane >> 2;      // 0..7
    const int q = lane & 3;       // 0..3
    const int wm = (warp >> 2) * 64;  // warp M base in tile
    const int wn = (warp & 3) * 32;   // warp N base in tile
    const int bm = blockIdx.y * 128;
    const int bn = blockIdx.x * 128;

    const int lr = tid >> 3;          // 0..31 (tile row)
    const int lc = (tid & 7) * 4;     // 0..28 (k offset, float4)

    float c[4][4][4];
#pragma unroll
    for (int mt = 0; mt < 4; mt++)
#pragma unroll
        for (int nt = 0; nt < 4; nt++)
#pragma unroll
            for (int i = 0; i < 4; i++) c[mt][nt][i] = 0.f;

    for (int k0 = 0; k0 < K; k0 += 32) {
#pragma unroll
        for (int i = 0; i < 4; i++) {
            const int r = lr + i * 32;
            float4 av = *(const float4*)&A[(size_t)(bm + r) * K + k0 + lc];
            float4 bv = *(const float4*)&B[(size_t)(bn + r) * K + k0 + lc];
            As[r][lc + 0] = f2tf(av.x);
            As[r][lc + 1] = f2tf(av.y);
            As[r][lc + 2] = f2tf(av.z);
            As[r][lc + 3] = f2tf(av.w);
            Bs[r][lc + 0] = f2tf(bv.x);
            Bs[r][lc + 1] = f2tf(bv.y);
            Bs[r][lc + 2] = f2tf(bv.z);
            Bs[r][lc + 3] = f2tf(bv.w);
        }
        __syncthreads();

#pragma unroll
        for (int ks = 0; ks < 4; ks++) {
            unsigned a[4][4], b[4][2];
#pragma unroll
            for (int mt = 0; mt < 4; mt++) {
                const int row = wm + mt * 16;
                a[mt][0] = As[row + g    ][ks * 8 + q    ];
                a[mt][1] = As[row + g + 8][ks * 8 + q    ];
                a[mt][2] = As[row + g    ][ks * 8 + q + 4];
                a[mt][3] = As[row + g + 8][ks * 8 + q + 4];
            }
#pragma unroll
            for (int nt = 0; nt < 4; nt++) {
                b[nt][0] = Bs[wn + nt * 8 + g][ks * 8 + q    ];
                b[nt][1] = Bs[wn + nt * 8 + g][ks * 8 + q + 4];
            }
#pragma unroll
            for (int mt = 0; mt < 4; mt++)
#pragma unroll
                for (int nt = 0; nt < 4; nt++)
                    mma_tf32(c[mt][nt], a[mt], b[nt]);
        }
        __syncthreads();
    }

    // Epilogue
#pragma unroll
    for (int mt = 0; mt < 4; mt++) {
        const int r0 = bm + wm + mt * 16 + g;
        const int r1 = r0 + 8;
#pragma unroll
        for (int nt = 0; nt < 4; nt++) {
            const int n0 = bn + wn + nt * 8 + 2 * q;
            const float bsum0 = bias[n0];
            const float bsum1 = bias[n0 + 1];
            float2 v0 = make_float2(c[mt][nt][0] + bsum0, c[mt][nt][1] + bsum1);
            float2 v1 = make_float2(c[mt][nt][2] + bsum0, c[mt][nt][3] + bsum1);
            if (MODE == 0) {
                *(float2*)&C[(size_t)r0 * N + n0] = v0;
                *(float2*)&C[(size_t)r1 * N + n0] = v1;
            } else {
                const int h = n0 >> 6, d = n0 & 63;
                const int b0 = r0 >> 11, s0 = r0 & 2047;
                const int b1 = r1 >> 11, s1 = r1 & 2047;
                *(float2*)&C[(((size_t)(b0 * HEADS + h)) * SEQ + s0) * HDIM + d] = v0;
                *(float2*)&C[(((size_t)(b1 * HEADS + h)) * SEQ + s1) * HDIM + d] = v1;
            }
        }
    }
}

// ---------------------------------------------------------------------------
// Flash attention with tf32 mma. Grid: (SEQ/64, B*H), 128 threads (4 warps).
// Each warp owns 16 query rows. K/V tiles of 64 keys staged in smem.
// ---------------------------------------------------------------------------
__global__ __launch_bounds__(128)
void attn_mma(const float* __restrict__ Q, const float* __restrict__ K,
              const float* __restrict__ V, float* __restrict__ O)
{
    __shared__ unsigned Ks[64][68];   // [key][dim], pad 4 -> QK B-frags conflict-free
    __shared__ unsigned Vs[64][72];   // [key][dim], pad 8 -> PV B-frags conflict-free

    const int bh  = blockIdx.y;           // b*HEADS + h
    const int q0  = blockIdx.x * 64;
    const int tid  = threadIdx.x;
    const int warp = tid >> 5;
    const int lane = tid & 31;
    const int g = lane >> 2;
    const int q = lane & 3;
    const float scale = 1.0f / 32.0f;      // 1/sqrt(EMB)

    const float* Qg = Q + ((size_t)bh * SEQ + q0) * HDIM;
    const float* Kg = K + (size_t)bh * SEQ * HDIM;
    const float* Vg = V + (size_t)bh * SEQ * HDIM;

    // Stage Q tile (scaled, tf32) through Ks, then pull A-fragments to regs.
#pragma unroll
    for (int i = 0; i < 8; i++) {
        const int f = tid + i * 128;          // 0..1023
        const int row = f >> 4;
        const int c4  = (f & 15) * 4;
        float4 v = *(const float4*)&Qg[row * HDIM + c4];
        Ks[row][c4 + 0] = f2tf(v.x * scale);
        Ks[row][c4 + 1] = f2tf(v.y * scale);
        Ks[row][c4 + 2] = f2tf(v.z * scale);
        Ks[row][c4 + 3] = f2tf(v.w * scale);
    }
    __syncthreads();

    unsigned qa[8][4];
#pragma unroll
    for (int ks = 0; ks < 8; ks++) {
        const int row = warp * 16;
        qa[ks][0] = Ks[row + g    ][ks * 8 + q    ];
        qa[ks][1] = Ks[row + g + 8][ks * 8 + q    ];
        qa[ks][2] = Ks[row + g    ][ks * 8 + q + 4];
        qa[ks][3] = Ks[row + g + 8][ks * 8 + q + 4];
    }
    __syncthreads();

    float o[8][4];
#pragma unroll
    for (int nt = 0; nt < 8; nt++)
#pragma unroll
        for (int i = 0; i < 4; i++) o[nt][i] = 0.f;
    float m0 = -1e30f, m1 = -1e30f, l0 = 0.f, l1 = 0.f;

    for (int kt = 0; kt < SEQ; kt += 64) {
        // Stage K/V tiles (tf32)
#pragma unroll
        for (int i = 0; i < 8; i++) {
            const int f = tid + i * 128;
            const int row = f >> 4;
            const int c4  = (f & 15) * 4;
            float4 kv = *(const float4*)&Kg[(size_t)(kt + row) * HDIM + c4];
            float4 vv = *(const float4*)&Vg[(size_t)(kt + row) * HDIM + c4];
            Ks[row][c4 + 0] = f2tf(kv.x);
            Ks[row][c4 + 1] = f2tf(kv.y);
            Ks[row][c4 + 2] = f2tf(kv.z);
            Ks[row][c4 + 3] = f2tf(kv.w);
            Vs[row][c4 + 0] = f2tf(vv.x);
            Vs[row][c4 + 1] = f2tf(vv.y);
            Vs[row][c4 + 2] = f2tf(vv.z);
            Vs[row][c4 + 3] = f2tf(vv.w);
        }
        __syncthreads();

        // S = Q * K^T  (nt: key groups of 8, ks: dim groups of 8)
        float s[8][4];
#pragma unroll
        for (int nt = 0; nt < 8; nt++) {
            s[nt][0] = 0.f; s[nt][1] = 0.f; s[nt][2] = 0.f; s[nt][3] = 0.f;
        }
#pragma unroll
        for (int nt = 0; nt < 8; nt++) {
#pragma unroll
            for (int ks = 0; ks < 8; ks++) {
                unsigned b[2];
                b[0] = Ks[nt * 8 + g][ks * 8 + q    ];
                b[1] = Ks[nt * 8 + g][ks * 8 + q + 4];
                mma_tf32(s[nt], qa[ks], b);
            }
        }

        // Online softmax (row r = lane>>2 : s[][0..1]; row r+8 : s[][2..3])
        float mx0 = -1e30f, mx1 = -1e30f;
#pragma unroll
        for (int nt = 0; nt < 8; nt++) {
            mx0 = fmaxf(mx0, fmaxf(s[nt][0], s[nt][1]));
            mx1 = fmaxf(mx1, fmaxf(s[nt][2], s[nt][3]));
        }
        mx0 = fmaxf(mx0, __shfl_xor_sync(0xffffffffu, mx0, 1));
        mx0 = fmaxf(mx0, __shfl_xor_sync(0xffffffffu, mx0, 2));
        mx1 = fmaxf(mx1, __shfl_xor_sync(0xffffffffu, mx1, 1));
        mx1 = fmaxf(mx1, __shfl_xor_sync(0xffffffffu, mx1, 2));

        const float nm0 = fmaxf(m0, mx0);
        const float nm1 = fmaxf(m1, mx1);
        const float cor0 = __expf(m0 - nm0);
        const float cor1 = __expf(m1 - nm1);
        m0 = nm0; m1 = nm1;

        float sum0 = 0.f, sum1 = 0.f;
#pragma unroll
        for (int nt = 0; nt < 8; nt++) {
            s[nt][0] = __expf(s[nt][0] - m0);
            s[nt][1] = __expf(s[nt][1] - m0);
            s[nt][2] = __expf(s[nt][2] - m1);
            s[nt][3] = __expf(s[nt][3] - m1);
            sum0 += s[nt][0] + s[nt][1];
            sum1 += s[nt][2] + s[nt][3];
        }
        sum0 += __shfl_xor_sync(0xffffffffu, sum0, 1);
        sum0 += __shfl_xor_sync(0xffffffffu, sum0, 2);
        sum1 += __shfl_xor_sync(0xffffffffu, sum1, 1);
        sum1 += __shfl_xor_sync(0xffffffffu, sum1, 2);
        l0 = l0 * cor0 + sum0;
        l1 = l1 * cor1 + sum1;

#pragma unroll
        for (int nt = 0; nt < 8; nt++) {
            o[nt][0] *= cor0; o[nt][1] *= cor0;
            o[nt][2] *= cor1; o[nt][3] *= cor1;
        }

        // O += P * V   (ks: key groups; A-frags rebuilt from C-frags via shfl)
        const int base = lane & ~3;
        const int src1 = base + (q >> 1);
        const int src2 = src1 + 2;
        const bool odd = (q & 1);
#pragma unroll
        for (int ks = 0; ks < 8; ks++) {
            float x0 = __shfl_sync(0xffffffffu, s[ks][0], src1);
            float x1 = __shfl_sync(0xffffffffu, s[ks][1], src1);
            float x2 = __shfl_sync(0xffffffffu, s[ks][2], src1);
            float x3 = __shfl_sync(0xffffffffu, s[ks][3], src1);
            float y0 = __shfl_sync(0xffffffffu, s[ks][0], src2);
            float y1 = __shfl_sync(0xffffffffu, s[ks][1], src2);
            float y2 = __shfl_sync(0xffffffffu, s[ks][2], src2);
            float y3 = __shfl_sync(0xffffffffu, s[ks][3], src2);
            unsigned a[4];
            a[0] = f2tf(odd ? x1 : x0);   // row r,   col q
            a[1] = f2tf(odd ? x3 : x2);   // row r+8, col q
            a[2] = f2tf(odd ? y1 : y0);   // row r,   col q+4
            a[3] = f2tf(odd ? y3 : y2);   // row r+8, col q+4
#pragma unroll
            for (int nt = 0; nt < 8; nt++) {
                unsigned b[2];
                b[0] = Vs[ks * 8 + q    ][nt * 8 + g];
                b[1] = Vs[ks * 8 + q + 4][nt * 8 + g];
                mma_tf32(o[nt], a, b);
            }
        }
        __syncthreads();
    }

    // Epilogue: normalize, write [B*S, E] with head offset
    const float inv0 = 1.0f / l0;
    const float inv1 = 1.0f / l1;
    const int b = bh >> 4;
    const int h = bh & 15;
    const int r0 = q0 + warp * 16 + g;
    const int r1 = r0 + 8;
#pragma unroll
    for (int nt = 0; nt < 8; nt++) {
        const int col = h * HDIM + nt * 8 + 2 * q;
        *(float2*)&O[((size_t)(b * SEQ + r0)) * EMB + col] =
            make_float2(o[nt][0] * inv0, o[nt][1] * inv0);
        *(float2*)&O[((size_t)(b * SEQ + r1)) * EMB + col] =
            make_float2(o[nt][2] * inv1, o[nt][3] * inv1);
    }
}

// ---------------------------------------------------------------------------
// Launch
// ---------------------------------------------------------------------------
extern "C" void kernel_launch(void* const* d_in, const int* in_sizes, int n_in,
                              void* d_out, int out_size)
{
    const float* x  = (const float*)d_in[0];
    const float* Wq = (const float*)d_in[1];
    const float* bq = (const float*)d_in[2];
    const float* Wk = (const float*)d_in[3];
    const float* bk = (const float*)d_in[4];
    const float* Wv = (const float*)d_in[5];
    const float* bv = (const float*)d_in[6];
    const float* Wo = (const float*)d_in[7];
    const float* bo = (const float*)d_in[8];
    float* out = (float*)d_out;

    float *dq, *dk, *dv, *doo;
    cudaGetSymbolAddress((void**)&dq,  g_q);
    cudaGetSymbolAddress((void**)&dk,  g_k);
    cudaGetSymbolAddress((void**)&dv,  g_v);
    cudaGetSymbolAddress((void**)&doo, g_o);

    dim3 ggrid(EMB / 128, MTOT / 128);   // (8, 64)
    gemm_tf32<1><<<ggrid, 256>>>(x, Wq, bq, dq, MTOT, EMB, EMB);
    gemm_tf32<1><<<ggrid, 256>>>(x, Wk, bk, dk, MTOT, EMB, EMB);
    gemm_tf32<1><<<ggrid, 256>>>(x, Wv, bv, dv, MTOT, EMB, EMB);

    dim3 agrid(SEQ / 64, BATCH * HEADS);  // (32, 64)
    attn_mma<<<agrid, 128>>>(dq, dk, dv, doo);

    gemm_tf32<0><<<ggrid, 256>>>(doo, Wo, bo, out, MTOT, EMB, EMB);
}